// round 6
// baseline (speedup 1.0000x reference)
#include <cuda_runtime.h>
#include <cuda_fp16.h>
#include <math.h>
#include <stdint.h>

// ---------------- problem constants ----------------
#define NHR_MAX 100000
#define F_IN 256
#define F_W 512
#define IN_MSG 1024
#define LN_EPS 1e-5f

// scratch: fp16 hi/lo activations, fp16 weights (hi only)
__device__ __half g_ah[(size_t)NHR_MAX * IN_MSG];
__device__ __half g_al[(size_t)NHR_MAX * IN_MSG];
__device__ __half g_bh[(size_t)NHR_MAX * F_W];
__device__ __half g_bl[(size_t)NHR_MAX * F_W];
__device__ __half g_w0[F_W * IN_MSG];
__device__ __half g_w1[F_W * F_W];
__device__ __half g_w2[F_W * F_W];
__device__ __half g_w3[F_W * F_W];
__device__ int g_idx_is64;

// ---------------- helpers ----------------
__device__ __forceinline__ uint32_t smem_u32(const void* p) {
    uint32_t a;
    asm("{ .reg .u64 t; cvta.to.shared.u64 t, %1; cvt.u32.u64 %0, t; }" : "=r"(a) : "l"(p));
    return a;
}
__device__ __forceinline__ float selu_f(float x) {
    const float sc = 1.0507009873554805f;
    const float al = 1.6732632423543772f;
    return x > 0.f ? sc * x : sc * al * expm1f(x);
}
__device__ __forceinline__ uint32_t f16x2_rn(float a, float b) {
    uint32_t r;
    asm("cvt.rn.f16x2.f32 %0, %1, %2;" : "=r"(r) : "f"(b), "f"(a));
    return r;
}
__device__ __forceinline__ float f16lo_to_f(uint32_t p) {
    return __half2float(__ushort_as_half((unsigned short)(p & 0xFFFFu)));
}
__device__ __forceinline__ float f16hi_to_f(uint32_t p) {
    return __half2float(__ushort_as_half((unsigned short)(p >> 16)));
}
__device__ __forceinline__ void ldmatrix_x4(uint32_t& r0, uint32_t& r1, uint32_t& r2, uint32_t& r3,
                                            uint32_t addr) {
    asm volatile("ldmatrix.sync.aligned.m8n8.x4.shared.b16 {%0,%1,%2,%3}, [%4];"
                 : "=r"(r0), "=r"(r1), "=r"(r2), "=r"(r3) : "r"(addr));
}
__device__ __forceinline__ void mma_f16(float* d, const uint32_t* a, const uint32_t* b) {
    asm volatile(
        "mma.sync.aligned.m16n8k16.row.col.f32.f16.f16.f32 "
        "{%0,%1,%2,%3}, {%4,%5,%6,%7}, {%8,%9}, {%0,%1,%2,%3};"
        : "+f"(d[0]), "+f"(d[1]), "+f"(d[2]), "+f"(d[3])
        : "r"(a[0]), "r"(a[1]), "r"(a[2]), "r"(a[3]), "r"(b[0]), "r"(b[1]));
}
__device__ __forceinline__ void cp_async16(uint32_t dst, const void* src, int szbytes) {
    asm volatile("cp.async.cg.shared.global [%0], [%1], 16, %2;"
                 :: "r"(dst), "l"(src), "r"(szbytes) : "memory");
}
#define CP_COMMIT() asm volatile("cp.async.commit_group;" ::: "memory")
#define CP_WAIT0()  asm volatile("cp.async.wait_group 0;" ::: "memory")

// ---------------- idx dtype detection ----------------
__global__ void detect_idx_kernel(const int* __restrict__ idx32) {
    int allzero = 1;
    for (int i = 1; i < 128; i += 2)
        if (idx32[i] != 0) { allzero = 0; break; }
    g_idx_is64 = allzero;
}

// ---------------- weight convert (fp16) ----------------
__global__ void wconv_kernel(const float* __restrict__ W,
                             __half* __restrict__ Wh, int n) {
    int i = blockIdx.x * blockDim.x + threadIdx.x;
    if (i < n) Wh[i] = __float2half_rn(W[i]);
}

// ---------------- prep ----------------
__global__ void __launch_bounds__(256)
prep_kernel(const float* __restrict__ v,
            const float* __restrict__ e_rel,
            const void*  __restrict__ idx_raw,
            const float* __restrict__ v_skip,
            const float* __restrict__ We,
            const float* __restrict__ be,
            const float* __restrict__ ln_g,
            const float* __restrict__ ln_b,
            int M) {
    int row = blockIdx.x;
    if (row >= M) return;
    int tid = threadIdx.x;

    long long src;
    if (g_idx_is64) src = ((const long long*)idx_raw)[row];
    else            src = (long long)(((const int*)idx_raw)[row]);

    float er = e_rel[row];

    float vals[4];
#pragma unroll
    for (int t = 0; t < 4; t++) {
        int j = tid + t * 256;
        float x;
        if (j < F_W)                 x = fmaf(-er, We[j], be[j]);
        else if (j < F_W + F_IN)     x = v[src * F_IN + (j - F_W)];
        else                         x = v_skip[(size_t)row * F_IN + (j - F_W - F_IN)];
        vals[t] = x;
    }

    float s  = vals[0] + vals[1] + vals[2] + vals[3];
    float s2 = vals[0]*vals[0] + vals[1]*vals[1] + vals[2]*vals[2] + vals[3]*vals[3];
#pragma unroll
    for (int o = 16; o > 0; o >>= 1) {
        s  += __shfl_xor_sync(0xFFFFFFFFu, s,  o);
        s2 += __shfl_xor_sync(0xFFFFFFFFu, s2, o);
    }
    __shared__ float red_s[8], red_s2[8];
    if ((tid & 31) == 0) { red_s[tid >> 5] = s; red_s2[tid >> 5] = s2; }
    __syncthreads();
    float sum = 0.f, sumsq = 0.f;
#pragma unroll
    for (int i = 0; i < 8; i++) { sum += red_s[i]; sumsq += red_s2[i]; }

    float mu   = sum * (1.0f / IN_MSG);
    float var  = sumsq * (1.0f / IN_MSG) - mu * mu;
    float rstd = rsqrtf(var + LN_EPS);

    __half* oh = g_ah + (size_t)row * IN_MSG;
    __half* ol = g_al + (size_t)row * IN_MSG;
#pragma unroll
    for (int t = 0; t < 4; t++) {
        int j = tid + t * 256;
        float y = fmaf((vals[t] - mu) * rstd, ln_g[j], ln_b[j]);
        __half h = __float2half_rn(y);
        oh[j] = h;
        ol[j] = __float2half_rn(y - __half2float(h));
    }
}

// ---------------- fp16 2-term GEMM: BK=64, 2-stage, 2 CTAs/SM ----------------
// out = selu((Ah+Al)[M,K] @ Wh[512,K]^T + bias)
#define BM 128
#define BN 128
#define BK 64
#define STAGES 2

#define PITCH 144          // 128B data + 16B pad (9x16B: conflict-free ldmatrix)
#define T_A_HI 0
#define T_A_LO 18432
#define T_B    36864
#define STAGE_B 55296
#define GEMM_SMEM (STAGES * STAGE_B)

__global__ void __launch_bounds__(256, 2)
gemm_f16x2_selu(const __half* __restrict__ Ah,
                const __half* __restrict__ Al,
                const __half* __restrict__ Wh,
                const float* __restrict__ bias,
                __half* __restrict__ Ch,
                __half* __restrict__ Cl,
                float* __restrict__ Cf,
                int M, int K) {
    extern __shared__ char smem[];
    uint32_t sb = smem_u32(smem);

    int tid = threadIdx.x;
    int wid = tid >> 5, lid = tid & 31;
    int warp_m = wid & 3;
    int warp_n = wid >> 2;
    int bm = blockIdx.y * BM;
    int bn = blockIdx.x * BN;

    // cp.async: thread -> (row = tid/2, 64B half of the 128B row); 4x16B per plane
    int g_row  = tid >> 1;
    int g_half = tid & 1;
    int a_sz = (bm + g_row) < M ? 16 : 0;
    const char* a_h_src = (const char*)(Ah + (size_t)(bm + g_row) * K) + g_half * 64;
    const char* a_l_src = (const char*)(Al + (size_t)(bm + g_row) * K) + g_half * 64;
    const char* b_src   = (const char*)(Wh + (size_t)(bn + g_row) * K) + g_half * 64;
    uint32_t dst_off = (uint32_t)(g_row * PITCH + g_half * 64);

    float acc[2][8][4];
#pragma unroll
    for (int i = 0; i < 2; i++)
#pragma unroll
        for (int j = 0; j < 8; j++)
#pragma unroll
            for (int q = 0; q < 4; q++) acc[i][j][q] = 0.f;

    // ldmatrix lane addressing
    int a_lrow = warp_m * 32 + (lid & 15);
    int a_lchk = (lid >> 4) * 16;
    uint32_t a_lm_off = (uint32_t)(a_lrow * PITCH + a_lchk);
    int b_lrow = warp_n * 64 + (lid & 7) + ((lid >> 4) << 3);
    int b_lchk = ((lid >> 3) & 1) * 16;
    uint32_t b_lm_off = (uint32_t)(b_lrow * PITCH + b_lchk);

    const int S = K / BK;

    // prologue: issue stage 0
    {
        uint32_t dst = sb + dst_off;
#pragma unroll
        for (int i = 0; i < 4; i++) {
            cp_async16(dst + T_A_HI + i * 16, a_h_src + i * 16, a_sz);
            cp_async16(dst + T_A_LO + i * 16, a_l_src + i * 16, a_sz);
            cp_async16(dst + T_B    + i * 16, b_src   + i * 16, 16);
        }
        CP_COMMIT();
    }

    for (int s = 0; s < S; s++) {
        CP_WAIT0();
        __syncthreads();   // stage s ready for all; slot (s+1)&1 free (compute s-1 done)

        // issue stage s+1 immediately: overlaps with compute below
        if (s + 1 < S) {
            int kb = (s + 1) * BK * 2;
            uint32_t dst = sb + ((s + 1) & 1) * STAGE_B + dst_off;
#pragma unroll
            for (int i = 0; i < 4; i++) {
                cp_async16(dst + T_A_HI + i * 16, a_h_src + kb + i * 16, a_sz);
                cp_async16(dst + T_A_LO + i * 16, a_l_src + kb + i * 16, a_sz);
                cp_async16(dst + T_B    + i * 16, b_src   + kb + i * 16, 16);
            }
        }
        CP_COMMIT();

        uint32_t tile = sb + (s & 1) * STAGE_B;
#pragma unroll
        for (int kk = 0; kk < 4; kk++) {
            uint32_t koff = kk * 32;
            uint32_t ahi[2][4], alo[2][4];
#pragma unroll
            for (int mf = 0; mf < 2; mf++) {
                uint32_t ad = tile + T_A_HI + a_lm_off + mf * (16 * PITCH) + koff;
                ldmatrix_x4(ahi[mf][0], ahi[mf][1], ahi[mf][2], ahi[mf][3], ad);
                ad = tile + T_A_LO + a_lm_off + mf * (16 * PITCH) + koff;
                ldmatrix_x4(alo[mf][0], alo[mf][1], alo[mf][2], alo[mf][3], ad);
            }
            uint32_t bh[8][2];
#pragma unroll
            for (int g = 0; g < 4; g++) {
                uint32_t bd = tile + T_B + b_lm_off + g * (16 * PITCH) + koff;
                ldmatrix_x4(bh[g*2][0], bh[g*2][1], bh[g*2+1][0], bh[g*2+1][1], bd);
            }
            // term-major: accumulator reuse distance 16
#pragma unroll
            for (int mf = 0; mf < 2; mf++)
#pragma unroll
                for (int nf = 0; nf < 8; nf++)
                    mma_f16(acc[mf][nf], ahi[mf], bh[nf]);
#pragma unroll
            for (int mf = 0; mf < 2; mf++)
#pragma unroll
                for (int nf = 0; nf < 8; nf++)
                    mma_f16(acc[mf][nf], alo[mf], bh[nf]);
        }
        __syncthreads();   // all warps done with slot (s&1) before it is refilled
    }

    // epilogue: bias + SELU; intermediates store fp16 hi/lo, last layer stores f32
    int tig = lid & 3, grp = lid >> 2;
#pragma unroll
    for (int nf = 0; nf < 8; nf++) {
        int col = bn + warp_n * 64 + nf * 8 + tig * 2;
        float bz0 = bias[col], bz1 = bias[col + 1];
#pragma unroll
        for (int mf = 0; mf < 2; mf++) {
            int row0 = bm + warp_m * 32 + mf * 16 + grp;
#pragma unroll
            for (int half = 0; half < 2; half++) {
                int row = row0 + half * 8;
                if (row < M) {
                    float o0 = selu_f(acc[mf][nf][half * 2 + 0] + bz0);
                    float o1 = selu_f(acc[mf][nf][half * 2 + 1] + bz1);
                    size_t off = (size_t)row * F_W + col;
                    if (Cf) {
                        *(float2*)(Cf + off) = make_float2(o0, o1);
                    } else {
                        uint32_t h = f16x2_rn(o0, o1);
                        float r0 = o0 - f16lo_to_f(h);
                        float r1 = o1 - f16hi_to_f(h);
                        uint32_t l = f16x2_rn(r0, r1);
                        *(uint32_t*)((char*)Ch + off * 2) = h;
                        *(uint32_t*)((char*)Cl + off * 2) = l;
                    }
                }
            }
        }
    }
}

// ---------------- launch ----------------
extern "C" void kernel_launch(void* const* d_in, const int* in_sizes, int n_in,
                              void* d_out, int out_size) {
    const float* v      = (const float*)d_in[0];
    const float* e_rel  = (const float*)d_in[1];
    const void*  idx    = (const void*) d_in[2];
    const float* v_skip = (const float*)d_in[3];
    const float* We     = (const float*)d_in[4];
    const float* be     = (const float*)d_in[5];
    const float* ln_g   = (const float*)d_in[6];
    const float* ln_b   = (const float*)d_in[7];
    const float* W0     = (const float*)d_in[8];
    const float* b0     = (const float*)d_in[9];
    const float* W1     = (const float*)d_in[10];
    const float* b1     = (const float*)d_in[11];
    const float* W2     = (const float*)d_in[12];
    const float* b2     = (const float*)d_in[13];
    const float* W3     = (const float*)d_in[14];
    const float* b3     = (const float*)d_in[15];

    int M = in_sizes[1];  // e_rel element count = N_HR

    __half *ah, *al, *bh, *bl, *w0, *w1, *w2, *w3;
    cudaGetSymbolAddress((void**)&ah, g_ah);
    cudaGetSymbolAddress((void**)&al, g_al);
    cudaGetSymbolAddress((void**)&bh, g_bh);
    cudaGetSymbolAddress((void**)&bl, g_bl);
    cudaGetSymbolAddress((void**)&w0, g_w0);
    cudaGetSymbolAddress((void**)&w1, g_w1);
    cudaGetSymbolAddress((void**)&w2, g_w2);
    cudaGetSymbolAddress((void**)&w3, g_w3);

    cudaFuncSetAttribute(gemm_f16x2_selu,
                         cudaFuncAttributeMaxDynamicSharedMemorySize, GEMM_SMEM);

    int n0 = F_W * IN_MSG, n1 = F_W * F_W;
    dim3 grid(F_W / BN, (M + BM - 1) / BM);

    // Launch order chosen so launch #6 (ncu -s 5 -c 1) is gemm0.
    detect_idx_kernel<<<1, 1>>>((const int*)idx);                  // 1
    wconv_kernel<<<(n0 + 255) / 256, 256>>>(W0, w0, n0);           // 2
    wconv_kernel<<<(n1 + 255) / 256, 256>>>(W1, w1, n1);           // 3
    wconv_kernel<<<(n1 + 255) / 256, 256>>>(W2, w2, n1);           // 4
    prep_kernel<<<M, 256>>>(v, e_rel, idx, v_skip, We, be, ln_g, ln_b, M);  // 5
    gemm_f16x2_selu<<<grid, 256, GEMM_SMEM>>>(ah, al, w0, b0, bh, bl, nullptr, M, IN_MSG); // 6
    wconv_kernel<<<(n1 + 255) / 256, 256>>>(W3, w3, n1);           // 7
    gemm_f16x2_selu<<<grid, 256, GEMM_SMEM>>>(bh, bl, w1, b1, ah, al, nullptr, M, F_W);    // 8
    gemm_f16x2_selu<<<grid, 256, GEMM_SMEM>>>(ah, al, w2, b2, bh, bl, nullptr, M, F_W);    // 9
    gemm_f16x2_selu<<<grid, 256, GEMM_SMEM>>>(bh, bl, w3, b3, nullptr, nullptr, (float*)d_out, M, F_W); // 10
}

// round 7
// speedup vs baseline: 1.2301x; 1.2301x over previous
#include <cuda_runtime.h>
#include <cuda_fp16.h>
#include <math.h>
#include <stdint.h>

// ---------------- problem constants ----------------
#define NHR_MAX 100000
#define F_IN 256
#define F_W 512
#define IN_MSG 1024
#define LN_EPS 1e-5f

// scratch: fp16 hi/lo activations, fp16 weights (hi only)
__device__ __half g_ah[(size_t)NHR_MAX * IN_MSG];
__device__ __half g_al[(size_t)NHR_MAX * IN_MSG];
__device__ __half g_bh[(size_t)NHR_MAX * F_W];
__device__ __half g_bl[(size_t)NHR_MAX * F_W];
__device__ __half g_w0[F_W * IN_MSG];
__device__ __half g_w1[F_W * F_W];
__device__ __half g_w2[F_W * F_W];
__device__ __half g_w3[F_W * F_W];
__device__ int g_idx_is64;

// ---------------- helpers ----------------
__device__ __forceinline__ uint32_t smem_u32(const void* p) {
    uint32_t a;
    asm("{ .reg .u64 t; cvta.to.shared.u64 t, %1; cvt.u32.u64 %0, t; }" : "=r"(a) : "l"(p));
    return a;
}
__device__ __forceinline__ float selu_f(float x) {
    const float sc = 1.0507009873554805f;
    const float al = 1.6732632423543772f;
    return x > 0.f ? sc * x : sc * al * expm1f(x);
}
__device__ __forceinline__ uint32_t f16x2_rn(float a, float b) {
    uint32_t r;
    asm("cvt.rn.f16x2.f32 %0, %1, %2;" : "=r"(r) : "f"(b), "f"(a));
    return r;
}
__device__ __forceinline__ float f16lo_to_f(uint32_t p) {
    return __half2float(__ushort_as_half((unsigned short)(p & 0xFFFFu)));
}
__device__ __forceinline__ float f16hi_to_f(uint32_t p) {
    return __half2float(__ushort_as_half((unsigned short)(p >> 16)));
}
__device__ __forceinline__ void ldmatrix_x4(uint32_t& r0, uint32_t& r1, uint32_t& r2, uint32_t& r3,
                                            uint32_t addr) {
    asm volatile("ldmatrix.sync.aligned.m8n8.x4.shared.b16 {%0,%1,%2,%3}, [%4];"
                 : "=r"(r0), "=r"(r1), "=r"(r2), "=r"(r3) : "r"(addr));
}
__device__ __forceinline__ void mma_f16(float* d, const uint32_t* a, const uint32_t* b) {
    asm volatile(
        "mma.sync.aligned.m16n8k16.row.col.f32.f16.f16.f32 "
        "{%0,%1,%2,%3}, {%4,%5,%6,%7}, {%8,%9}, {%0,%1,%2,%3};"
        : "+f"(d[0]), "+f"(d[1]), "+f"(d[2]), "+f"(d[3])
        : "r"(a[0]), "r"(a[1]), "r"(a[2]), "r"(a[3]), "r"(b[0]), "r"(b[1]));
}
__device__ __forceinline__ void cp_async16(uint32_t dst, const void* src, int szbytes) {
    asm volatile("cp.async.cg.shared.global [%0], [%1], 16, %2;"
                 :: "r"(dst), "l"(src), "r"(szbytes) : "memory");
}
#define CP_COMMIT() asm volatile("cp.async.commit_group;" ::: "memory")
#define CP_WAIT1()  asm volatile("cp.async.wait_group 1;" ::: "memory")

// ---------------- idx dtype detection ----------------
__global__ void detect_idx_kernel(const int* __restrict__ idx32) {
    int allzero = 1;
    for (int i = 1; i < 128; i += 2)
        if (idx32[i] != 0) { allzero = 0; break; }
    g_idx_is64 = allzero;
}

// ---------------- weight convert (fp16) ----------------
__global__ void wconv_kernel(const float* __restrict__ W,
                             __half* __restrict__ Wh, int n) {
    int i = blockIdx.x * blockDim.x + threadIdx.x;
    if (i < n) Wh[i] = __float2half_rn(W[i]);
}

// ---------------- prep ----------------
__global__ void __launch_bounds__(256)
prep_kernel(const float* __restrict__ v,
            const float* __restrict__ e_rel,
            const void*  __restrict__ idx_raw,
            const float* __restrict__ v_skip,
            const float* __restrict__ We,
            const float* __restrict__ be,
            const float* __restrict__ ln_g,
            const float* __restrict__ ln_b,
            int M) {
    int row = blockIdx.x;
    if (row >= M) return;
    int tid = threadIdx.x;

    long long src;
    if (g_idx_is64) src = ((const long long*)idx_raw)[row];
    else            src = (long long)(((const int*)idx_raw)[row]);

    float er = e_rel[row];

    float vals[4];
#pragma unroll
    for (int t = 0; t < 4; t++) {
        int j = tid + t * 256;
        float x;
        if (j < F_W)                 x = fmaf(-er, We[j], be[j]);
        else if (j < F_W + F_IN)     x = v[src * F_IN + (j - F_W)];
        else                         x = v_skip[(size_t)row * F_IN + (j - F_W - F_IN)];
        vals[t] = x;
    }

    float s  = vals[0] + vals[1] + vals[2] + vals[3];
    float s2 = vals[0]*vals[0] + vals[1]*vals[1] + vals[2]*vals[2] + vals[3]*vals[3];
#pragma unroll
    for (int o = 16; o > 0; o >>= 1) {
        s  += __shfl_xor_sync(0xFFFFFFFFu, s,  o);
        s2 += __shfl_xor_sync(0xFFFFFFFFu, s2, o);
    }
    __shared__ float red_s[8], red_s2[8];
    if ((tid & 31) == 0) { red_s[tid >> 5] = s; red_s2[tid >> 5] = s2; }
    __syncthreads();
    float sum = 0.f, sumsq = 0.f;
#pragma unroll
    for (int i = 0; i < 8; i++) { sum += red_s[i]; sumsq += red_s2[i]; }

    float mu   = sum * (1.0f / IN_MSG);
    float var  = sumsq * (1.0f / IN_MSG) - mu * mu;
    float rstd = rsqrtf(var + LN_EPS);

    __half* oh = g_ah + (size_t)row * IN_MSG;
    __half* ol = g_al + (size_t)row * IN_MSG;
#pragma unroll
    for (int t = 0; t < 4; t++) {
        int j = tid + t * 256;
        float y = fmaf((vals[t] - mu) * rstd, ln_g[j], ln_b[j]);
        __half h = __float2half_rn(y);
        oh[j] = h;
        ol[j] = __float2half_rn(y - __half2float(h));
    }
}

// ---------------- fp16 2-term GEMM (cp.async, 3-stage, early-issue) ----------------
// out = selu((Ah+Al)[M,K] @ Wh[512,K]^T + bias)
// CTA tile 128x128, BK=32; 8 warps (4m x 2n), warp tile 32x64; 2 CTAs/SM.
#define BM 128
#define BN 128
#define BK 32
#define STAGES 3

#define PITCH 80           // 64B data + 16B pad: conflict-free ldmatrix
#define T_A_HI 0
#define T_A_LO 10240
#define T_B    20480
#define STAGE_B 30720
#define GEMM_SMEM (STAGES * STAGE_B)

__global__ void __launch_bounds__(256, 2)
gemm_f16x2_selu(const __half* __restrict__ Ah,
                const __half* __restrict__ Al,
                const __half* __restrict__ Wh,
                const float* __restrict__ bias,
                __half* __restrict__ Ch,
                __half* __restrict__ Cl,
                float* __restrict__ Cf,
                int M, int K) {
    extern __shared__ char smem[];
    uint32_t sb = smem_u32(smem);

    int tid = threadIdx.x;
    int wid = tid >> 5, lid = tid & 31;
    int warp_m = wid & 3;
    int warp_n = wid >> 2;
    int bm = blockIdx.y * BM;
    int bn = blockIdx.x * BN;

    // cp.async mapping: thread -> (row = tid/2, 32B half of the 64B row)
    int g_row  = tid >> 1;
    int g_half = tid & 1;
    int a_sz = (bm + g_row) < M ? 16 : 0;
    const char* a_h_src = (const char*)(Ah + (size_t)(bm + g_row) * K) + g_half * 32;
    const char* a_l_src = (const char*)(Al + (size_t)(bm + g_row) * K) + g_half * 32;
    const char* b_src   = (const char*)(Wh + (size_t)(bn + g_row) * K) + g_half * 32;
    uint32_t dst_off = (uint32_t)(g_row * PITCH + g_half * 32);

    float acc[2][8][4];
#pragma unroll
    for (int i = 0; i < 2; i++)
#pragma unroll
        for (int j = 0; j < 8; j++)
#pragma unroll
            for (int q = 0; q < 4; q++) acc[i][j][q] = 0.f;

    // ldmatrix lane addressing
    int a_lrow = warp_m * 32 + (lid & 15);
    int a_lchk = (lid >> 4) * 16;
    uint32_t a_lm_off = (uint32_t)(a_lrow * PITCH + a_lchk);
    int b_lrow = warp_n * 64 + (lid & 7) + ((lid >> 4) << 3);
    int b_lchk = ((lid >> 3) & 1) * 16;
    uint32_t b_lm_off = (uint32_t)(b_lrow * PITCH + b_lchk);

    const int S = K / BK;

    // prologue: issue stages 0, 1
#pragma unroll
    for (int s = 0; s < STAGES - 1; s++) {
        int kb = s * BK * 2;
        uint32_t dst = sb + s * STAGE_B + dst_off;
        cp_async16(dst + T_A_HI,      a_h_src + kb,      a_sz);
        cp_async16(dst + T_A_HI + 16, a_h_src + kb + 16, a_sz);
        cp_async16(dst + T_A_LO,      a_l_src + kb,      a_sz);
        cp_async16(dst + T_A_LO + 16, a_l_src + kb + 16, a_sz);
        cp_async16(dst + T_B,         b_src + kb,        16);
        cp_async16(dst + T_B + 16,    b_src + kb + 16,   16);
        CP_COMMIT();
    }

    for (int s = 0; s < S; s++) {
        CP_WAIT1();        // stage s landed (one newer group stays in flight)
        __syncthreads();   // stage s visible to all; slot of stage s-1 now free

        // early-issue stage s+2 into stage (s-1)'s slot: 2 compute blocks to hide
        int sn = s + STAGES - 1;
        if (sn < S) {
            int kb = sn * BK * 2;
            uint32_t dst = sb + (sn % STAGES) * STAGE_B + dst_off;
            cp_async16(dst + T_A_HI,      a_h_src + kb,      a_sz);
            cp_async16(dst + T_A_HI + 16, a_h_src + kb + 16, a_sz);
            cp_async16(dst + T_A_LO,      a_l_src + kb,      a_sz);
            cp_async16(dst + T_A_LO + 16, a_l_src + kb + 16, a_sz);
            cp_async16(dst + T_B,         b_src + kb,        16);
            cp_async16(dst + T_B + 16,    b_src + kb + 16,   16);
        }
        CP_COMMIT();       // unconditional: wait_group accounting stays exact

        uint32_t tile = sb + (s % STAGES) * STAGE_B;
#pragma unroll
        for (int kk = 0; kk < 2; kk++) {
            uint32_t koff = kk * 32;
            uint32_t ahi[2][4], alo[2][4];
#pragma unroll
            for (int mf = 0; mf < 2; mf++) {
                uint32_t ad = tile + T_A_HI + a_lm_off + mf * (16 * PITCH) + koff;
                ldmatrix_x4(ahi[mf][0], ahi[mf][1], ahi[mf][2], ahi[mf][3], ad);
                ad = tile + T_A_LO + a_lm_off + mf * (16 * PITCH) + koff;
                ldmatrix_x4(alo[mf][0], alo[mf][1], alo[mf][2], alo[mf][3], ad);
            }
            uint32_t bh[8][2];
#pragma unroll
            for (int g = 0; g < 4; g++) {
                uint32_t bd = tile + T_B + b_lm_off + g * (16 * PITCH) + koff;
                ldmatrix_x4(bh[g*2][0], bh[g*2][1], bh[g*2+1][0], bh[g*2+1][1], bd);
            }
            // term-major: accumulator reuse distance 16
#pragma unroll
            for (int mf = 0; mf < 2; mf++)
#pragma unroll
                for (int nf = 0; nf < 8; nf++)
                    mma_f16(acc[mf][nf], ahi[mf], bh[nf]);
#pragma unroll
            for (int mf = 0; mf < 2; mf++)
#pragma unroll
                for (int nf = 0; nf < 8; nf++)
                    mma_f16(acc[mf][nf], alo[mf], bh[nf]);
        }
    }

    // epilogue: bias + SELU; intermediates store fp16 hi/lo, last layer stores f32
    int tig = lid & 3, grp = lid >> 2;
#pragma unroll
    for (int nf = 0; nf < 8; nf++) {
        int col = bn + warp_n * 64 + nf * 8 + tig * 2;
        float bz0 = bias[col], bz1 = bias[col + 1];
#pragma unroll
        for (int mf = 0; mf < 2; mf++) {
            int row0 = bm + warp_m * 32 + mf * 16 + grp;
#pragma unroll
            for (int half = 0; half < 2; half++) {
                int row = row0 + half * 8;
                if (row < M) {
                    float o0 = selu_f(acc[mf][nf][half * 2 + 0] + bz0);
                    float o1 = selu_f(acc[mf][nf][half * 2 + 1] + bz1);
                    size_t off = (size_t)row * F_W + col;
                    if (Cf) {
                        *(float2*)(Cf + off) = make_float2(o0, o1);
                    } else {
                        uint32_t h = f16x2_rn(o0, o1);
                        float r0 = o0 - f16lo_to_f(h);
                        float r1 = o1 - f16hi_to_f(h);
                        uint32_t l = f16x2_rn(r0, r1);
                        *(uint32_t*)((char*)Ch + off * 2) = h;
                        *(uint32_t*)((char*)Cl + off * 2) = l;
                    }
                }
            }
        }
    }
}

// ---------------- launch ----------------
extern "C" void kernel_launch(void* const* d_in, const int* in_sizes, int n_in,
                              void* d_out, int out_size) {
    const float* v      = (const float*)d_in[0];
    const float* e_rel  = (const float*)d_in[1];
    const void*  idx    = (const void*) d_in[2];
    const float* v_skip = (const float*)d_in[3];
    const float* We     = (const float*)d_in[4];
    const float* be     = (const float*)d_in[5];
    const float* ln_g   = (const float*)d_in[6];
    const float* ln_b   = (const float*)d_in[7];
    const float* W0     = (const float*)d_in[8];
    const float* b0     = (const float*)d_in[9];
    const float* W1     = (const float*)d_in[10];
    const float* b1     = (const float*)d_in[11];
    const float* W2     = (const float*)d_in[12];
    const float* b2     = (const float*)d_in[13];
    const float* W3     = (const float*)d_in[14];
    const float* b3     = (const float*)d_in[15];

    int M = in_sizes[1];  // e_rel element count = N_HR

    __half *ah, *al, *bh, *bl, *w0, *w1, *w2, *w3;
    cudaGetSymbolAddress((void**)&ah, g_ah);
    cudaGetSymbolAddress((void**)&al, g_al);
    cudaGetSymbolAddress((void**)&bh, g_bh);
    cudaGetSymbolAddress((void**)&bl, g_bl);
    cudaGetSymbolAddress((void**)&w0, g_w0);
    cudaGetSymbolAddress((void**)&w1, g_w1);
    cudaGetSymbolAddress((void**)&w2, g_w2);
    cudaGetSymbolAddress((void**)&w3, g_w3);

    cudaFuncSetAttribute(gemm_f16x2_selu,
                         cudaFuncAttributeMaxDynamicSharedMemorySize, GEMM_SMEM);

    int n0 = F_W * IN_MSG, n1 = F_W * F_W;
    dim3 grid(F_W / BN, (M + BM - 1) / BM);

    detect_idx_kernel<<<1, 1>>>((const int*)idx);
    prep_kernel<<<M, 256>>>(v, e_rel, idx, v_skip, We, be, ln_g, ln_b, M);
    wconv_kernel<<<(n0 + 255) / 256, 256>>>(W0, w0, n0);
    wconv_kernel<<<(n1 + 255) / 256, 256>>>(W1, w1, n1);
    wconv_kernel<<<(n1 + 255) / 256, 256>>>(W2, w2, n1);
    wconv_kernel<<<(n1 + 255) / 256, 256>>>(W3, w3, n1);

    gemm_f16x2_selu<<<grid, 256, GEMM_SMEM>>>(ah, al, w0, b0, bh, bl, nullptr, M, IN_MSG);
    gemm_f16x2_selu<<<grid, 256, GEMM_SMEM>>>(bh, bl, w1, b1, ah, al, nullptr, M, F_W);
    gemm_f16x2_selu<<<grid, 256, GEMM_SMEM>>>(ah, al, w2, b2, bh, bl, nullptr, M, F_W);
    gemm_f16x2_selu<<<grid, 256, GEMM_SMEM>>>(bh, bl, w3, b3, nullptr, nullptr, (float*)d_out, M, F_W);
}

// round 8
// speedup vs baseline: 1.9461x; 1.5821x over previous
#include <cuda_runtime.h>
#include <cuda_fp16.h>
#include <math.h>
#include <stdint.h>

// ---------------- problem constants ----------------
#define NHR_MAX 100000
#define F_IN 256
#define F_W 512
#define IN_MSG 1024
#define LN_EPS 1e-5f

// scratch: fp16 activations (single plane), fp16 weights
__device__ __half g_a[(size_t)NHR_MAX * IN_MSG];
__device__ __half g_b[(size_t)NHR_MAX * F_W];
__device__ __half g_w0[F_W * IN_MSG];
__device__ __half g_w1[F_W * F_W];
__device__ __half g_w2[F_W * F_W];
__device__ __half g_w3[F_W * F_W];
__device__ int g_idx_is64;

// ---------------- helpers ----------------
__device__ __forceinline__ uint32_t smem_u32(const void* p) {
    uint32_t a;
    asm("{ .reg .u64 t; cvta.to.shared.u64 t, %1; cvt.u32.u64 %0, t; }" : "=r"(a) : "l"(p));
    return a;
}
__device__ __forceinline__ float selu_f(float x) {
    const float sc = 1.0507009873554805f;
    const float al = 1.6732632423543772f;
    return x > 0.f ? sc * x : sc * al * expm1f(x);
}
__device__ __forceinline__ uint32_t f16x2_rn(float a, float b) {
    uint32_t r;
    asm("cvt.rn.f16x2.f32 %0, %1, %2;" : "=r"(r) : "f"(b), "f"(a));
    return r;
}
__device__ __forceinline__ void ldmatrix_x4(uint32_t& r0, uint32_t& r1, uint32_t& r2, uint32_t& r3,
                                            uint32_t addr) {
    asm volatile("ldmatrix.sync.aligned.m8n8.x4.shared.b16 {%0,%1,%2,%3}, [%4];"
                 : "=r"(r0), "=r"(r1), "=r"(r2), "=r"(r3) : "r"(addr));
}
__device__ __forceinline__ void mma_f16(float* d, const uint32_t* a, const uint32_t* b) {
    asm volatile(
        "mma.sync.aligned.m16n8k16.row.col.f32.f16.f16.f32 "
        "{%0,%1,%2,%3}, {%4,%5,%6,%7}, {%8,%9}, {%0,%1,%2,%3};"
        : "+f"(d[0]), "+f"(d[1]), "+f"(d[2]), "+f"(d[3])
        : "r"(a[0]), "r"(a[1]), "r"(a[2]), "r"(a[3]), "r"(b[0]), "r"(b[1]));
}
__device__ __forceinline__ void cp_async16(uint32_t dst, const void* src, int szbytes) {
    asm volatile("cp.async.cg.shared.global [%0], [%1], 16, %2;"
                 :: "r"(dst), "l"(src), "r"(szbytes) : "memory");
}
#define CP_COMMIT() asm volatile("cp.async.commit_group;" ::: "memory")
#define CP_WAIT2()  asm volatile("cp.async.wait_group 2;" ::: "memory")

// ---------------- idx dtype detection ----------------
__global__ void detect_idx_kernel(const int* __restrict__ idx32) {
    int allzero = 1;
    for (int i = 1; i < 128; i += 2)
        if (idx32[i] != 0) { allzero = 0; break; }
    g_idx_is64 = allzero;
}

// ---------------- weight convert (fp16) ----------------
__global__ void wconv_kernel(const float* __restrict__ W,
                             __half* __restrict__ Wh, int n) {
    int i = blockIdx.x * blockDim.x + threadIdx.x;
    if (i < n) Wh[i] = __float2half_rn(W[i]);
}

// ---------------- prep: edge-enc | gather | skip, LayerNorm, fp16 ----------------
__global__ void __launch_bounds__(256)
prep_kernel(const float* __restrict__ v,
            const float* __restrict__ e_rel,
            const void*  __restrict__ idx_raw,
            const float* __restrict__ v_skip,
            const float* __restrict__ We,
            const float* __restrict__ be,
            const float* __restrict__ ln_g,
            const float* __restrict__ ln_b,
            int M) {
    int row = blockIdx.x;
    if (row >= M) return;
    int tid = threadIdx.x;

    long long src;
    if (g_idx_is64) src = ((const long long*)idx_raw)[row];
    else            src = (long long)(((const int*)idx_raw)[row]);

    float er = e_rel[row];

    float vals[4];
#pragma unroll
    for (int t = 0; t < 4; t++) {
        int j = tid + t * 256;
        float x;
        if (j < F_W)                 x = fmaf(-er, We[j], be[j]);
        else if (j < F_W + F_IN)     x = v[src * F_IN + (j - F_W)];
        else                         x = v_skip[(size_t)row * F_IN + (j - F_W - F_IN)];
        vals[t] = x;
    }

    float s  = vals[0] + vals[1] + vals[2] + vals[3];
    float s2 = vals[0]*vals[0] + vals[1]*vals[1] + vals[2]*vals[2] + vals[3]*vals[3];
#pragma unroll
    for (int o = 16; o > 0; o >>= 1) {
        s  += __shfl_xor_sync(0xFFFFFFFFu, s,  o);
        s2 += __shfl_xor_sync(0xFFFFFFFFu, s2, o);
    }
    __shared__ float red_s[8], red_s2[8];
    if ((tid & 31) == 0) { red_s[tid >> 5] = s; red_s2[tid >> 5] = s2; }
    __syncthreads();
    float sum = 0.f, sumsq = 0.f;
#pragma unroll
    for (int i = 0; i < 8; i++) { sum += red_s[i]; sumsq += red_s2[i]; }

    float mu   = sum * (1.0f / IN_MSG);
    float var  = sumsq * (1.0f / IN_MSG) - mu * mu;
    float rstd = rsqrtf(var + LN_EPS);

    __half* oh = g_a + (size_t)row * IN_MSG;
#pragma unroll
    for (int t = 0; t < 4; t++) {
        int j = tid + t * 256;
        float y = fmaf((vals[t] - mu) * rstd, ln_g[j], ln_b[j]);
        oh[j] = __float2half_rn(y);
    }
}

// ---------------- fp16 GEMM (cp.async, 4-stage, wait2, issue-after-compute) ----
// out = selu(A[M,K] @ W[512,K]^T + bias), A/W fp16, fp32 accumulate.
// CTA tile 128x128, BK=32; 8 warps (4m x 2n), warp tile 32x64; 2 CTAs/SM.
#define BM 128
#define BN 128
#define BK 32
#define STAGES 4

#define PITCH 80           // 64B data + 16B pad: conflict-free ldmatrix
#define T_A 0
#define T_B 10240
#define STAGE_B 20480
#define GEMM_SMEM (STAGES * STAGE_B)

__global__ void __launch_bounds__(256, 2)
gemm_f16_selu(const __half* __restrict__ A,
              const __half* __restrict__ W,
              const float* __restrict__ bias,
              __half* __restrict__ Ch,
              float* __restrict__ Cf,
              int M, int K) {
    extern __shared__ char smem[];
    uint32_t sb = smem_u32(smem);

    int tid = threadIdx.x;
    int wid = tid >> 5, lid = tid & 31;
    int warp_m = wid & 3;
    int warp_n = wid >> 2;
    int bm = blockIdx.y * BM;
    int bn = blockIdx.x * BN;

    // cp.async mapping: thread -> (row = tid/2, 32B half of the 64B row)
    int g_row  = tid >> 1;
    int g_half = tid & 1;
    int a_sz = (bm + g_row) < M ? 16 : 0;
    const char* a_src = (const char*)(A + (size_t)(bm + g_row) * K) + g_half * 32;
    const char* b_src = (const char*)(W + (size_t)(bn + g_row) * K) + g_half * 32;
    uint32_t dst_off = (uint32_t)(g_row * PITCH + g_half * 32);

    float acc[2][8][4];
#pragma unroll
    for (int i = 0; i < 2; i++)
#pragma unroll
        for (int j = 0; j < 8; j++)
#pragma unroll
            for (int q = 0; q < 4; q++) acc[i][j][q] = 0.f;

    // ldmatrix lane addressing (validated R3-R7)
    int a_lrow = warp_m * 32 + (lid & 15);
    int a_lchk = (lid >> 4) * 16;
    uint32_t a_lm_off = (uint32_t)(a_lrow * PITCH + a_lchk);
    int b_lrow = warp_n * 64 + (lid & 7) + ((lid >> 4) << 3);
    int b_lchk = ((lid >> 3) & 1) * 16;
    uint32_t b_lm_off = (uint32_t)(b_lrow * PITCH + b_lchk);

    const int S = K / BK;

    // prologue: issue stages 0..2
#pragma unroll
    for (int s = 0; s < STAGES - 1; s++) {
        int kb = s * BK * 2;
        uint32_t dst = sb + s * STAGE_B + dst_off;
        cp_async16(dst + T_A,      a_src + kb,      a_sz);
        cp_async16(dst + T_A + 16, a_src + kb + 16, a_sz);
        cp_async16(dst + T_B,      b_src + kb,      16);
        cp_async16(dst + T_B + 16, b_src + kb + 16, 16);
        CP_COMMIT();
    }

    for (int s = 0; s < S; s++) {
        CP_WAIT2();        // stage s landed; 2 newer groups may remain in flight
        __syncthreads();   // stage s visible to all warps

        uint32_t tile = sb + (s % STAGES) * STAGE_B;
#pragma unroll
        for (int kk = 0; kk < 2; kk++) {
            uint32_t koff = kk * 32;
            uint32_t af[2][4];
#pragma unroll
            for (int mf = 0; mf < 2; mf++) {
                uint32_t ad = tile + T_A + a_lm_off + mf * (16 * PITCH) + koff;
                ldmatrix_x4(af[mf][0], af[mf][1], af[mf][2], af[mf][3], ad);
            }
            uint32_t bf[8][2];
#pragma unroll
            for (int g = 0; g < 4; g++) {
                uint32_t bd = tile + T_B + b_lm_off + g * (16 * PITCH) + koff;
                ldmatrix_x4(bf[g*2][0], bf[g*2][1], bf[g*2+1][0], bf[g*2+1][1], bd);
            }
#pragma unroll
            for (int mf = 0; mf < 2; mf++)
#pragma unroll
                for (int nf = 0; nf < 8; nf++)
                    mma_f16(acc[mf][nf], af[mf], bf[nf]);
        }

        // issue stage s+3 into the slot of stage s-1 (free: its compute finished)
        int sn = s + STAGES - 1;
        if (sn < S) {
            int kb = sn * BK * 2;
            uint32_t dst = sb + (sn % STAGES) * STAGE_B + dst_off;
            cp_async16(dst + T_A,      a_src + kb,      a_sz);
            cp_async16(dst + T_A + 16, a_src + kb + 16, a_sz);
            cp_async16(dst + T_B,      b_src + kb,      16);
            cp_async16(dst + T_B + 16, b_src + kb + 16, 16);
        }
        CP_COMMIT();       // unconditional: wait_group accounting stays exact
    }

    // epilogue: bias + SELU; intermediates store fp16, last layer stores f32
    int tig = lid & 3, grp = lid >> 2;
#pragma unroll
    for (int nf = 0; nf < 8; nf++) {
        int col = bn + warp_n * 64 + nf * 8 + tig * 2;
        float bz0 = bias[col], bz1 = bias[col + 1];
#pragma unroll
        for (int mf = 0; mf < 2; mf++) {
            int row0 = bm + warp_m * 32 + mf * 16 + grp;
#pragma unroll
            for (int half = 0; half < 2; half++) {
                int row = row0 + half * 8;
                if (row < M) {
                    float o0 = selu_f(acc[mf][nf][half * 2 + 0] + bz0);
                    float o1 = selu_f(acc[mf][nf][half * 2 + 1] + bz1);
                    size_t off = (size_t)row * F_W + col;
                    if (Cf) {
                        *(float2*)(Cf + off) = make_float2(o0, o1);
                    } else {
                        *(uint32_t*)((char*)Ch + off * 2) = f16x2_rn(o0, o1);
                    }
                }
            }
        }
    }
}

// ---------------- launch ----------------
extern "C" void kernel_launch(void* const* d_in, const int* in_sizes, int n_in,
                              void* d_out, int out_size) {
    const float* v      = (const float*)d_in[0];
    const float* e_rel  = (const float*)d_in[1];
    const void*  idx    = (const void*) d_in[2];
    const float* v_skip = (const float*)d_in[3];
    const float* We     = (const float*)d_in[4];
    const float* be     = (const float*)d_in[5];
    const float* ln_g   = (const float*)d_in[6];
    const float* ln_b   = (const float*)d_in[7];
    const float* W0     = (const float*)d_in[8];
    const float* b0     = (const float*)d_in[9];
    const float* W1     = (const float*)d_in[10];
    const float* b1     = (const float*)d_in[11];
    const float* W2     = (const float*)d_in[12];
    const float* b2     = (const float*)d_in[13];
    const float* W3     = (const float*)d_in[14];
    const float* b3     = (const float*)d_in[15];

    int M = in_sizes[1];  // e_rel element count = N_HR

    __half *a, *b, *w0, *w1, *w2, *w3;
    cudaGetSymbolAddress((void**)&a,  g_a);
    cudaGetSymbolAddress((void**)&b,  g_b);
    cudaGetSymbolAddress((void**)&w0, g_w0);
    cudaGetSymbolAddress((void**)&w1, g_w1);
    cudaGetSymbolAddress((void**)&w2, g_w2);
    cudaGetSymbolAddress((void**)&w3, g_w3);

    cudaFuncSetAttribute(gemm_f16_selu,
                         cudaFuncAttributeMaxDynamicSharedMemorySize, GEMM_SMEM);

    int n0 = F_W * IN_MSG, n1 = F_W * F_W;
    dim3 grid(F_W / BN, (M + BM - 1) / BM);

    detect_idx_kernel<<<1, 1>>>((const int*)idx);
    prep_kernel<<<M, 256>>>(v, e_rel, idx, v_skip, We, be, ln_g, ln_b, M);
    wconv_kernel<<<(n0 + 255) / 256, 256>>>(W0, w0, n0);
    wconv_kernel<<<(n1 + 255) / 256, 256>>>(W1, w1, n1);
    wconv_kernel<<<(n1 + 255) / 256, 256>>>(W2, w2, n1);
    wconv_kernel<<<(n1 + 255) / 256, 256>>>(W3, w3, n1);

    gemm_f16_selu<<<grid, 256, GEMM_SMEM>>>(a, w0, b0, b, nullptr, M, IN_MSG);
    gemm_f16_selu<<<grid, 256, GEMM_SMEM>>>(b, w1, b1, a, nullptr, M, F_W);
    gemm_f16_selu<<<grid, 256, GEMM_SMEM>>>(a, w2, b2, b, nullptr, M, F_W);
    gemm_f16_selu<<<grid, 256, GEMM_SMEM>>>(b, w3, b3, nullptr, (float*)d_out, M, F_W);
}